// round 1
// baseline (speedup 1.0000x reference)
#include <cuda_runtime.h>
#include <cuda_bf16.h>
#include <math.h>

// ---------------------------------------------------------------------------
// FastMKAAttention — fp32 baseline
// shapes: b=2, t=1024, d=2048, h=16, dh=128
// output tuple layout (floats): out[4194304] | kh[4194304] | vh[4194304] | lam[6144]
// ---------------------------------------------------------------------------

#define B_   2
#define T_   1024
#define D_   2048
#define H_   16
#define DH_  128

// scratch (device globals; allocation-free per harness rules)
__device__ float g_q[B_*T_*D_];      // x @ wq^T  (unscaled)
__device__ float g_l2[B_*T_*D_];     // EMA
__device__ float g_hdn[B_*T_*(D_/2)];// silu(q @ rw1^T + rb1)
__device__ float g_fused[B_*T_*D_];
__device__ float g_attn[B_*T_*D_];   // attention output in [b,t,d] layout

// ---------------------------------------------------------------------------
// Generic SGEMM:  C[m,n] = act( sum_k A[m,k]*B[n,k] (+bias[n]) )
// A: [M,K] row-major,  B: [N,K] row-major (i.e. X @ W^T with W[N,K]).
// MODE 0: C row-major [M,N].  MODE 1: write as [b,h,t,dh] (b=m>>10,t=m&1023,
//         h=n>>7,dh=n&127) — used to emit kh/vh directly.
// ACT 0: none.  ACT 1: bias + silu.
// BM=BN=128, BK=16, 256 threads, 8x8 per thread.
// ---------------------------------------------------------------------------
#define GBM 128
#define GBN 128
#define GBK 16

template<int MODE, int ACT>
__global__ __launch_bounds__(256) void sgemm_tn(
    const float* __restrict__ A, const float* __restrict__ Bm,
    const float* __restrict__ bias, float* __restrict__ C,
    int M, int N, int K)
{
    __shared__ float As[GBK][GBM + 4];
    __shared__ float Bs[GBK][GBN + 4];

    const int tid = threadIdx.x;
    const int bm = blockIdx.y * GBM;
    const int bn = blockIdx.x * GBN;

    const int wid  = tid >> 5;
    const int lane = tid & 31;
    const int m0 = (wid & 3) * 32 + (lane & 3) * 8;
    const int n0 = (wid >> 2) * 64 + (lane >> 2) * 8;

    float acc[8][8];
#pragma unroll
    for (int i = 0; i < 8; i++)
#pragma unroll
        for (int j = 0; j < 8; j++) acc[i][j] = 0.f;

    for (int kt = 0; kt < K; kt += GBK) {
        // cooperative loads: 128 rows x 16 k each for A and B tile
#pragma unroll
        for (int p = 0; p < 2; p++) {
            int f = p * 256 + tid;
            int row  = f >> 2;
            int quad = f & 3;
            float4 av = *(const float4*)&A [(bm + row) * K + kt + quad * 4];
            float4 bv = *(const float4*)&Bm[(bn + row) * K + kt + quad * 4];
            As[quad*4+0][row] = av.x; As[quad*4+1][row] = av.y;
            As[quad*4+2][row] = av.z; As[quad*4+3][row] = av.w;
            Bs[quad*4+0][row] = bv.x; Bs[quad*4+1][row] = bv.y;
            Bs[quad*4+2][row] = bv.z; Bs[quad*4+3][row] = bv.w;
        }
        __syncthreads();

#pragma unroll
        for (int k = 0; k < GBK; k++) {
            float4 a0 = *(const float4*)&As[k][m0];
            float4 a1 = *(const float4*)&As[k][m0 + 4];
            float4 b0 = *(const float4*)&Bs[k][n0];
            float4 b1 = *(const float4*)&Bs[k][n0 + 4];
            float ar[8] = {a0.x,a0.y,a0.z,a0.w,a1.x,a1.y,a1.z,a1.w};
            float br[8] = {b0.x,b0.y,b0.z,b0.w,b1.x,b1.y,b1.z,b1.w};
#pragma unroll
            for (int i = 0; i < 8; i++)
#pragma unroll
                for (int j = 0; j < 8; j++)
                    acc[i][j] += ar[i] * br[j];
        }
        __syncthreads();
    }

    // epilogue
#pragma unroll
    for (int i = 0; i < 8; i++) {
        int m = bm + m0 + i;
#pragma unroll
        for (int jq = 0; jq < 2; jq++) {
            int n = bn + n0 + jq * 4;
            float4 v;
            v.x = acc[i][jq*4+0]; v.y = acc[i][jq*4+1];
            v.z = acc[i][jq*4+2]; v.w = acc[i][jq*4+3];
            if (ACT == 1) {
                v.x += bias[n+0]; v.y += bias[n+1]; v.z += bias[n+2]; v.w += bias[n+3];
                v.x = v.x / (1.f + __expf(-v.x));
                v.y = v.y / (1.f + __expf(-v.y));
                v.z = v.z / (1.f + __expf(-v.z));
                v.w = v.w / (1.f + __expf(-v.w));
            }
            if (MODE == 0) {
                *(float4*)&C[m * N + n] = v;
            } else {
                // [b,h,t,dh]: b=m>>10, t=m&1023, h=n>>7, dh=n&127
                int idx = (m >> 10) * (H_*T_*DH_) + (n >> 7) * (T_*DH_)
                        + (m & 1023) * DH_ + (n & 127);
                *(float4*)&C[idx] = v;
            }
        }
    }
}

// ---------------------------------------------------------------------------
// causal EMA: one thread per (b, d) channel; 1024 serial steps
// ---------------------------------------------------------------------------
__global__ void ema_kernel(const float* __restrict__ x, float* __restrict__ l2)
{
    int idx = blockIdx.x * blockDim.x + threadIdx.x;  // 0..4095
    int b = idx >> 11;
    int d = idx & (D_ - 1);
    const float beta = 0.9f, omb = 0.1f;
    size_t p = (size_t)b * T_ * D_ + d;
    float s = 0.f;
#pragma unroll 4
    for (int t = 0; t < T_; t++) {
        s = beta * s + omb * x[p];
        l2[p] = s;
        p += D_;
    }
}

// ---------------------------------------------------------------------------
// router (logits -> softmax over 3) + fused combine.
// one block per row m (b*t rows), 256 threads.
// ---------------------------------------------------------------------------
__global__ __launch_bounds__(256) void router_fuse(
    const float* __restrict__ hdn, const float* __restrict__ rw2,
    const float* __restrict__ rb2, const float* __restrict__ x,
    const float* __restrict__ l2, const float* __restrict__ l3m,
    float* __restrict__ lam_out, float* __restrict__ fused)
{
    const int m = blockIdx.x;
    const int tid = threadIdx.x;
    const int HD = D_ / 2;  // 1024

    const float* hrow = hdn + (size_t)m * HD;
    float s0 = 0.f, s1 = 0.f, s2 = 0.f;
    for (int k = tid; k < HD; k += 256) {
        float hv = hrow[k];
        s0 += hv * rw2[k];
        s1 += hv * rw2[HD + k];
        s2 += hv * rw2[2*HD + k];
    }
#pragma unroll
    for (int o = 16; o > 0; o >>= 1) {
        s0 += __shfl_down_sync(0xffffffffu, s0, o);
        s1 += __shfl_down_sync(0xffffffffu, s1, o);
        s2 += __shfl_down_sync(0xffffffffu, s2, o);
    }
    __shared__ float red[8][3];
    __shared__ float lam_s[3];
    if ((tid & 31) == 0) {
        red[tid >> 5][0] = s0; red[tid >> 5][1] = s1; red[tid >> 5][2] = s2;
    }
    __syncthreads();
    if (tid == 0) {
        float L0 = rb2[0], L1 = rb2[1], L2v = rb2[2];
        for (int w = 0; w < 8; w++) { L0 += red[w][0]; L1 += red[w][1]; L2v += red[w][2]; }
        float mx = fmaxf(L0, fmaxf(L1, L2v));
        float e0 = __expf(L0 - mx), e1 = __expf(L1 - mx), e2 = __expf(L2v - mx);
        float inv = 1.f / (e0 + e1 + e2);
        lam_s[0] = e0 * inv; lam_s[1] = e1 * inv; lam_s[2] = e2 * inv;
        lam_out[m*3+0] = lam_s[0]; lam_out[m*3+1] = lam_s[1]; lam_out[m*3+2] = lam_s[2];
    }
    __syncthreads();
    const float la = lam_s[0], lb = lam_s[1], lc = lam_s[2];
    const int b = m >> 10;
    const float4* xr  = (const float4*)(x  + (size_t)m * D_);
    const float4* l2r = (const float4*)(l2 + (size_t)m * D_);
    const float4* l3r = (const float4*)(l3m + (size_t)b * D_);
    float4* fr = (float4*)(fused + (size_t)m * D_);
    for (int q = tid; q < D_/4; q += 256) {
        float4 xv = xr[q], l2v = l2r[q], l3v = l3r[q], o;
        o.x = la*xv.x + lb*l2v.x + lc*l3v.x;
        o.y = la*xv.y + lb*l2v.y + lc*l3v.y;
        o.z = la*xv.z + lb*l2v.z + lc*l3v.z;
        o.w = la*xv.w + lb*l2v.w + lc*l3v.w;
        fr[q] = o;
    }
}

// ---------------------------------------------------------------------------
// flash-style causal attention. BM=BN=64, dh=128, 256 threads.
// grid: (t/64, b*h). reads q (unscaled, [b,t,d]) and kh/vh ([b,h,t,dh]
// already written into the output buffer). writes to g_attn in [b,t,d].
// dyn smem: Q/K/V tiles stride 132 + S[64][65] + stats = 118784 B
// ---------------------------------------------------------------------------
#define ATT_SMEM ((3*64*132 + 64*65 + 3*64) * 4)

__global__ __launch_bounds__(256) void attn_kernel(
    const float* __restrict__ qsrc, const float* __restrict__ kh,
    const float* __restrict__ vh, float* __restrict__ osrc)
{
    extern __shared__ float sm[];
    float* Qs  = sm;                 // 64 * 132
    float* Ks  = Qs + 64*132;
    float* Vs  = Ks + 64*132;
    float* Ss  = Vs + 64*132;        // 64 * 65
    float* m_s = Ss + 64*65;
    float* l_s = m_s + 64;
    float* al_s= l_s + 64;

    const int tid = threadIdx.x;
    const int qt = blockIdx.x, bh = blockIdx.y;
    const int b = bh >> 4, h = bh & 15;
    const int q0 = qt * 64;
    const float scale = 0.08838834764831845f;  // 1/sqrt(128)

    // load Q tile (scaled)
#pragma unroll
    for (int p = 0; p < 8; p++) {
        int f = p * 256 + tid;
        int i = f >> 5, c4 = f & 31;
        float4 v = *(const float4*)&qsrc[(size_t)(b*T_ + q0 + i)*D_ + h*DH_ + c4*4];
        v.x *= scale; v.y *= scale; v.z *= scale; v.w *= scale;
        *(float4*)&Qs[i*132 + c4*4] = v;
    }
    if (tid < 64) { m_s[tid] = -1e30f; l_s[tid] = 0.f; }

    float acc[32];
#pragma unroll
    for (int c = 0; c < 32; c++) acc[c] = 0.f;

    const int i_sc = tid >> 2;   // row 0..63
    const int jg   = tid & 3;    // 16-key group for scores
    const int ck   = tid & 3;    // 32-dim chunk for acc

    const float* kbase = kh + (size_t)(b*H_ + h) * T_ * DH_;
    const float* vbase = vh + (size_t)(b*H_ + h) * T_ * DH_;

    for (int kt = 0; kt <= qt; kt++) {
        __syncthreads();  // protect Ks/Vs/Ss from previous iteration
#pragma unroll
        for (int p = 0; p < 8; p++) {
            int f = p * 256 + tid;
            int j = f >> 5, c4 = f & 31;
            *(float4*)&Ks[j*132 + c4*4] = *(const float4*)&kbase[(size_t)(kt*64 + j)*DH_ + c4*4];
            *(float4*)&Vs[j*132 + c4*4] = *(const float4*)&vbase[(size_t)(kt*64 + j)*DH_ + c4*4];
        }
        __syncthreads();

        // scores: thread (i_sc, jg) computes 16 dots of length 128
        float sum[16];
#pragma unroll
        for (int jj = 0; jj < 16; jj++) sum[jj] = 0.f;
        const float4* qrow = (const float4*)&Qs[i_sc * 132];
        for (int c4 = 0; c4 < 32; c4++) {
            float4 qv = qrow[c4];
#pragma unroll
            for (int jj = 0; jj < 16; jj++) {
                float4 kv = *(const float4*)&Ks[(jg*16 + jj)*132 + c4*4];
                sum[jj] += qv.x*kv.x + qv.y*kv.y + qv.z*kv.z + qv.w*kv.w;
            }
        }
        const int gq = q0 + i_sc;
#pragma unroll
        for (int jj = 0; jj < 16; jj++) {
            int j = jg*16 + jj;
            int gk = kt*64 + j;
            Ss[i_sc*65 + j] = (gk <= gq) ? sum[jj] : -1e30f;
        }
        __syncthreads();

        // online softmax bookkeeping: one thread per row
        if (tid < 64) {
            float* row = &Ss[tid * 65];
            float mo = m_s[tid];
            float mloc = mo;
            for (int j = 0; j < 64; j++) mloc = fmaxf(mloc, row[j]);
            float alpha = __expf(mo - mloc);
            float ls = 0.f;
            for (int j = 0; j < 64; j++) {
                float pv = __expf(row[j] - mloc);
                row[j] = pv; ls += pv;
            }
            m_s[tid]  = mloc;
            l_s[tid]  = l_s[tid] * alpha + ls;
            al_s[tid] = alpha;
        }
        __syncthreads();

        // acc update: thread (i_sc, ck) owns 32 dims of its row
        float al = al_s[i_sc];
#pragma unroll
        for (int c = 0; c < 32; c++) acc[c] *= al;
        const float* srow = &Ss[i_sc * 65];
        for (int j = 0; j < 64; j++) {
            float pv = srow[j];
            const float4* vrow = (const float4*)&Vs[j*132 + ck*32];
#pragma unroll
            for (int c4 = 0; c4 < 8; c4++) {
                float4 vv = vrow[c4];
                acc[c4*4+0] += pv * vv.x;
                acc[c4*4+1] += pv * vv.y;
                acc[c4*4+2] += pv * vv.z;
                acc[c4*4+3] += pv * vv.w;
            }
        }
    }
    __syncthreads();
    const float inv = 1.f / l_s[i_sc];
    float* obase = osrc + (size_t)(b*T_ + q0 + i_sc)*D_ + h*DH_ + ck*32;
#pragma unroll
    for (int c4 = 0; c4 < 8; c4++) {
        float4 v;
        v.x = acc[c4*4+0]*inv; v.y = acc[c4*4+1]*inv;
        v.z = acc[c4*4+2]*inv; v.w = acc[c4*4+3]*inv;
        *(float4*)&obase[c4*4] = v;
    }
}

// ---------------------------------------------------------------------------
extern "C" void kernel_launch(void* const* d_in, const int* in_sizes, int n_in,
                              void* d_out, int out_size)
{
    const float* x   = (const float*)d_in[0];
    const float* l3m = (const float*)d_in[1];
    const float* wq  = (const float*)d_in[2];
    const float* wk  = (const float*)d_in[3];
    const float* wv  = (const float*)d_in[4];
    const float* wo  = (const float*)d_in[5];
    const float* rw1 = (const float*)d_in[6];
    const float* rb1 = (const float*)d_in[7];
    const float* rw2 = (const float*)d_in[8];
    const float* rb2 = (const float*)d_in[9];

    float* out  = (float*)d_out;
    float* khp  = out + (size_t)B_*T_*D_;        //  4194304
    float* vhp  = khp + (size_t)B_*T_*D_;        //  8388608
    float* lamp = vhp + (size_t)B_*T_*D_;        // 12582912

    float *qs, *l2s, *hdns, *fuseds, *attns;
    cudaGetSymbolAddress((void**)&qs,     g_q);
    cudaGetSymbolAddress((void**)&l2s,    g_l2);
    cudaGetSymbolAddress((void**)&hdns,   g_hdn);
    cudaGetSymbolAddress((void**)&fuseds, g_fused);
    cudaGetSymbolAddress((void**)&attns,  g_attn);

    dim3 blk(256);

    // q = x @ wq^T
    sgemm_tn<0,0><<<dim3(D_/GBN, (B_*T_)/GBM), blk>>>(x, wq, nullptr, qs, B_*T_, D_, D_);
    // l2 = causal EMA(x)
    ema_kernel<<<16, 256>>>(x, l2s);
    // hdn = silu(q @ rw1^T + rb1)
    sgemm_tn<0,1><<<dim3((D_/2)/GBN, (B_*T_)/GBM), blk>>>(qs, rw1, rb1, hdns, B_*T_, D_/2, D_);
    // lam + fused
    router_fuse<<<B_*T_, 256>>>(hdns, rw2, rb2, x, l2s, l3m, lamp, fuseds);
    // kh, vh (written transposed directly into output buffer)
    sgemm_tn<1,0><<<dim3(D_/GBN, (B_*T_)/GBM), blk>>>(fuseds, wk, nullptr, khp, B_*T_, D_, D_);
    sgemm_tn<1,0><<<dim3(D_/GBN, (B_*T_)/GBM), blk>>>(fuseds, wv, nullptr, vhp, B_*T_, D_, D_);
    // attention
    cudaFuncSetAttribute(attn_kernel, cudaFuncAttributeMaxDynamicSharedMemorySize, ATT_SMEM);
    attn_kernel<<<dim3(T_/64, B_*H_), blk, ATT_SMEM>>>(qs, khp, vhp, attns);
    // out = attn @ wo^T
    sgemm_tn<0,0><<<dim3(D_/GBN, (B_*T_)/GBM), blk>>>(attns, wo, nullptr, out, B_*T_, D_, D_);
}

// round 2
// speedup vs baseline: 1.2186x; 1.2186x over previous
#include <cuda_runtime.h>
#include <cuda_bf16.h>
#include <math.h>

// ---------------------------------------------------------------------------
// FastMKAAttention — round 2: all GEMMs on tensor cores (bf16x3 split mma)
// shapes: b=2, t=1024, d=2048, h=16, dh=128
// output tuple layout (floats): out[4194304] | kh[4194304] | vh[4194304] | lam[6144]
// ---------------------------------------------------------------------------

#define B_   2
#define T_   1024
#define D_   2048
#define H_   16
#define DH_  128

// scratch (device globals; allocation-free per harness rules)
__device__ float g_q[B_*T_*D_];      // x @ wq^T  (unscaled)
__device__ float g_l2[B_*T_*D_];     // EMA
__device__ float g_hdn[B_*T_*(D_/2)];// silu(q @ rw1^T + rb1)
__device__ float g_fused[B_*T_*D_];
__device__ float g_attn[B_*T_*D_];   // attention output in [b,t,d] layout

// ---------------------------------------------------------------------------
// Tensor-core GEMM, bf16x3 split precision:
//   C[m,n] = act( sum_k A[m,k]*B[n,k] (+bias[n]) )
// A: [M,K] row-major fp32,  B: [N,K] row-major fp32 (X @ W^T, W=[N,K]).
// Each fp32 value v is split v = hi + lo (bf16 each); accumulate
// hi*hi + hi*lo + lo*hi in fp32 via mma.sync.m16n8k16.bf16.
// MODE 0: C row-major [M,N].  MODE 1: scatter as [b,h,t,dh].
// ACT 0: none.  ACT 1: bias + silu.
// Block tile 128x128, BK=32, 256 threads = 8 warps (2x4), warp tile 64x32.
// ---------------------------------------------------------------------------
#define SSTR 40   // smem row stride in bf16 elems (conflict-free frag loads)

__device__ __forceinline__ void mma_bf16(float* c, const unsigned* a, const unsigned* b) {
    asm volatile(
        "mma.sync.aligned.m16n8k16.row.col.f32.bf16.bf16.f32 "
        "{%0,%1,%2,%3}, {%4,%5,%6,%7}, {%8,%9}, {%0,%1,%2,%3};\n"
        : "+f"(c[0]), "+f"(c[1]), "+f"(c[2]), "+f"(c[3])
        : "r"(a[0]), "r"(a[1]), "r"(a[2]), "r"(a[3]), "r"(b[0]), "r"(b[1]));
}

template<int MODE, int ACT>
__global__ __launch_bounds__(256) void mma_gemm_tn(
    const float* __restrict__ A, const float* __restrict__ Bm,
    const float* __restrict__ bias, float* __restrict__ C,
    int M, int N, int K)
{
    __shared__ __nv_bfloat16 As_hi[128*SSTR];
    __shared__ __nv_bfloat16 As_lo[128*SSTR];
    __shared__ __nv_bfloat16 Bs_hi[128*SSTR];
    __shared__ __nv_bfloat16 Bs_lo[128*SSTR];

    const int tid  = threadIdx.x;
    const int lane = tid & 31;
    const int wid  = tid >> 5;
    const int wm   = wid >> 2;       // 0..1 -> m offset wm*64
    const int wn   = wid & 3;        // 0..3 -> n offset wn*32
    const int bm   = blockIdx.y * 128;
    const int bn   = blockIdx.x * 128;

    float acc[4][4][4];
#pragma unroll
    for (int i = 0; i < 4; i++)
#pragma unroll
        for (int j = 0; j < 4; j++)
#pragma unroll
            for (int r = 0; r < 4; r++) acc[i][j][r] = 0.f;

    for (int kt = 0; kt < K; kt += 32) {
        // ---- stage: global fp32 -> smem bf16 hi/lo (128 rows x 32 cols each) ----
#pragma unroll
        for (int it = 0; it < 4; it++) {
            int f = it * 256 + tid;          // 0..1023
            int row = f >> 3;
            int q   = f & 7;
            float4 av = *(const float4*)&A [(size_t)(bm + row) * K + kt + q * 4];
            float4 bv = *(const float4*)&Bm[(size_t)(bn + row) * K + kt + q * 4];
            const float ae[4] = {av.x, av.y, av.z, av.w};
            const float be[4] = {bv.x, bv.y, bv.z, bv.w};
#pragma unroll
            for (int e = 0; e < 4; e++) {
                int col = q * 4 + e;
                __nv_bfloat16 ah = __float2bfloat16(ae[e]);
                __nv_bfloat16 al = __float2bfloat16(ae[e] - __bfloat162float(ah));
                __nv_bfloat16 bh = __float2bfloat16(be[e]);
                __nv_bfloat16 bl = __float2bfloat16(be[e] - __bfloat162float(bh));
                As_hi[row * SSTR + col] = ah;
                As_lo[row * SSTR + col] = al;
                Bs_hi[row * SSTR + col] = bh;
                Bs_lo[row * SSTR + col] = bl;
            }
        }
        __syncthreads();

        // ---- compute: 2 k-steps of 16 ----
#pragma unroll
        for (int ks = 0; ks < 2; ks++) {
            const int kk = ks * 16 + (lane & 3) * 2;

            unsigned ahi[4][4], alo[4][4];
#pragma unroll
            for (int mf = 0; mf < 4; mf++) {
                int r0 = (wm * 64 + mf * 16 + (lane >> 2)) * SSTR;
                int r1 = r0 + 8 * SSTR;
                ahi[mf][0] = *(const unsigned*)&As_hi[r0 + kk];
                ahi[mf][1] = *(const unsigned*)&As_hi[r1 + kk];
                ahi[mf][2] = *(const unsigned*)&As_hi[r0 + kk + 8];
                ahi[mf][3] = *(const unsigned*)&As_hi[r1 + kk + 8];
                alo[mf][0] = *(const unsigned*)&As_lo[r0 + kk];
                alo[mf][1] = *(const unsigned*)&As_lo[r1 + kk];
                alo[mf][2] = *(const unsigned*)&As_lo[r0 + kk + 8];
                alo[mf][3] = *(const unsigned*)&As_lo[r1 + kk + 8];
            }
            unsigned bhi[4][2], blo[4][2];
#pragma unroll
            for (int nf = 0; nf < 4; nf++) {
                int c0 = (wn * 32 + nf * 8 + (lane >> 2)) * SSTR;
                bhi[nf][0] = *(const unsigned*)&Bs_hi[c0 + kk];
                bhi[nf][1] = *(const unsigned*)&Bs_hi[c0 + kk + 8];
                blo[nf][0] = *(const unsigned*)&Bs_lo[c0 + kk];
                blo[nf][1] = *(const unsigned*)&Bs_lo[c0 + kk + 8];
            }
#pragma unroll
            for (int mf = 0; mf < 4; mf++)
#pragma unroll
                for (int nf = 0; nf < 4; nf++) {
                    mma_bf16(acc[mf][nf], ahi[mf], bhi[nf]);
                    mma_bf16(acc[mf][nf], ahi[mf], blo[nf]);
                    mma_bf16(acc[mf][nf], alo[mf], bhi[nf]);
                }
        }
        __syncthreads();
    }

    // ---- epilogue ----
#pragma unroll
    for (int mf = 0; mf < 4; mf++) {
#pragma unroll
        for (int nf = 0; nf < 4; nf++) {
            int m0 = bm + wm * 64 + mf * 16 + (lane >> 2);
            int n  = bn + wn * 32 + nf * 8 + (lane & 3) * 2;
#pragma unroll
            for (int half = 0; half < 2; half++) {
                int m = m0 + half * 8;
                float2 v;
                v.x = acc[mf][nf][half * 2 + 0];
                v.y = acc[mf][nf][half * 2 + 1];
                if (ACT == 1) {
                    v.x += bias[n];
                    v.y += bias[n + 1];
                    v.x = v.x / (1.f + __expf(-v.x));
                    v.y = v.y / (1.f + __expf(-v.y));
                }
                if (MODE == 0) {
                    *(float2*)&C[(size_t)m * N + n] = v;
                } else {
                    // [b,h,t,dh]: b=m>>10, t=m&1023, h=n>>7, dh=n&127
                    size_t idx = (size_t)(m >> 10) * (H_*T_*DH_) + (size_t)(n >> 7) * (T_*DH_)
                               + (size_t)(m & 1023) * DH_ + (n & 127);
                    *(float2*)&C[idx] = v;
                }
            }
        }
    }
}

// ---------------------------------------------------------------------------
// causal EMA: one thread per (b, d) channel; 1024 serial steps
// ---------------------------------------------------------------------------
__global__ void ema_kernel(const float* __restrict__ x, float* __restrict__ l2)
{
    int idx = blockIdx.x * blockDim.x + threadIdx.x;  // 0..4095
    int b = idx >> 11;
    int d = idx & (D_ - 1);
    const float beta = 0.9f, omb = 0.1f;
    size_t p = (size_t)b * T_ * D_ + d;
    float s = 0.f;
#pragma unroll 4
    for (int t = 0; t < T_; t++) {
        s = beta * s + omb * x[p];
        l2[p] = s;
        p += D_;
    }
}

// ---------------------------------------------------------------------------
// router (logits -> softmax over 3) + fused combine.
// one block per row m (b*t rows), 256 threads.
// ---------------------------------------------------------------------------
__global__ __launch_bounds__(256) void router_fuse(
    const float* __restrict__ hdn, const float* __restrict__ rw2,
    const float* __restrict__ rb2, const float* __restrict__ x,
    const float* __restrict__ l2, const float* __restrict__ l3m,
    float* __restrict__ lam_out, float* __restrict__ fused)
{
    const int m = blockIdx.x;
    const int tid = threadIdx.x;
    const int HD = D_ / 2;  // 1024

    const float* hrow = hdn + (size_t)m * HD;
    float s0 = 0.f, s1 = 0.f, s2 = 0.f;
    for (int k = tid; k < HD; k += 256) {
        float hv = hrow[k];
        s0 += hv * rw2[k];
        s1 += hv * rw2[HD + k];
        s2 += hv * rw2[2*HD + k];
    }
#pragma unroll
    for (int o = 16; o > 0; o >>= 1) {
        s0 += __shfl_down_sync(0xffffffffu, s0, o);
        s1 += __shfl_down_sync(0xffffffffu, s1, o);
        s2 += __shfl_down_sync(0xffffffffu, s2, o);
    }
    __shared__ float red[8][3];
    __shared__ float lam_s[3];
    if ((tid & 31) == 0) {
        red[tid >> 5][0] = s0; red[tid >> 5][1] = s1; red[tid >> 5][2] = s2;
    }
    __syncthreads();
    if (tid == 0) {
        float L0 = rb2[0], L1 = rb2[1], L2v = rb2[2];
        for (int w = 0; w < 8; w++) { L0 += red[w][0]; L1 += red[w][1]; L2v += red[w][2]; }
        float mx = fmaxf(L0, fmaxf(L1, L2v));
        float e0 = __expf(L0 - mx), e1 = __expf(L1 - mx), e2 = __expf(L2v - mx);
        float inv = 1.f / (e0 + e1 + e2);
        lam_s[0] = e0 * inv; lam_s[1] = e1 * inv; lam_s[2] = e2 * inv;
        lam_out[m*3+0] = lam_s[0]; lam_out[m*3+1] = lam_s[1]; lam_out[m*3+2] = lam_s[2];
    }
    __syncthreads();
    const float la = lam_s[0], lb = lam_s[1], lc = lam_s[2];
    const int b = m >> 10;
    const float4* xr  = (const float4*)(x  + (size_t)m * D_);
    const float4* l2r = (const float4*)(l2 + (size_t)m * D_);
    const float4* l3r = (const float4*)(l3m + (size_t)b * D_);
    float4* fr = (float4*)(fused + (size_t)m * D_);
    for (int q = tid; q < D_/4; q += 256) {
        float4 xv = xr[q], l2v = l2r[q], l3v = l3r[q], o;
        o.x = la*xv.x + lb*l2v.x + lc*l3v.x;
        o.y = la*xv.y + lb*l2v.y + lc*l3v.y;
        o.z = la*xv.z + lb*l2v.z + lc*l3v.z;
        o.w = la*xv.w + lb*l2v.w + lc*l3v.w;
        fr[q] = o;
    }
}

// ---------------------------------------------------------------------------
// flash-style causal attention. BM=BN=64, dh=128, 256 threads.
// grid: (t/64, b*h). reads q (unscaled, [b,t,d]) and kh/vh ([b,h,t,dh]
// already written into the output buffer). writes to g_attn in [b,t,d].
// ---------------------------------------------------------------------------
#define ATT_SMEM ((3*64*132 + 64*65 + 3*64) * 4)

__global__ __launch_bounds__(256) void attn_kernel(
    const float* __restrict__ qsrc, const float* __restrict__ kh,
    const float* __restrict__ vh, float* __restrict__ osrc)
{
    extern __shared__ float sm[];
    float* Qs  = sm;                 // 64 * 132
    float* Ks  = Qs + 64*132;
    float* Vs  = Ks + 64*132;
    float* Ss  = Vs + 64*132;        // 64 * 65
    float* m_s = Ss + 64*65;
    float* l_s = m_s + 64;
    float* al_s= l_s + 64;

    const int tid = threadIdx.x;
    const int qt = blockIdx.x, bh = blockIdx.y;
    const int b = bh >> 4, h = bh & 15;
    const int q0 = qt * 64;
    const float scale = 0.08838834764831845f;  // 1/sqrt(128)

    // load Q tile (scaled)
#pragma unroll
    for (int p = 0; p < 8; p++) {
        int f = p * 256 + tid;
        int i = f >> 5, c4 = f & 31;
        float4 v = *(const float4*)&qsrc[(size_t)(b*T_ + q0 + i)*D_ + h*DH_ + c4*4];
        v.x *= scale; v.y *= scale; v.z *= scale; v.w *= scale;
        *(float4*)&Qs[i*132 + c4*4] = v;
    }
    if (tid < 64) { m_s[tid] = -1e30f; l_s[tid] = 0.f; }

    float acc[32];
#pragma unroll
    for (int c = 0; c < 32; c++) acc[c] = 0.f;

    const int i_sc = tid >> 2;   // row 0..63
    const int jg   = tid & 3;    // 16-key group for scores
    const int ck   = tid & 3;    // 32-dim chunk for acc

    const float* kbase = kh + (size_t)(b*H_ + h) * T_ * DH_;
    const float* vbase = vh + (size_t)(b*H_ + h) * T_ * DH_;

    for (int kt = 0; kt <= qt; kt++) {
        __syncthreads();  // protect Ks/Vs/Ss from previous iteration
#pragma unroll
        for (int p = 0; p < 8; p++) {
            int f = p * 256 + tid;
            int j = f >> 5, c4 = f & 31;
            *(float4*)&Ks[j*132 + c4*4] = *(const float4*)&kbase[(size_t)(kt*64 + j)*DH_ + c4*4];
            *(float4*)&Vs[j*132 + c4*4] = *(const float4*)&vbase[(size_t)(kt*64 + j)*DH_ + c4*4];
        }
        __syncthreads();

        // scores: thread (i_sc, jg) computes 16 dots of length 128
        float sum[16];
#pragma unroll
        for (int jj = 0; jj < 16; jj++) sum[jj] = 0.f;
        const float4* qrow = (const float4*)&Qs[i_sc * 132];
        for (int c4 = 0; c4 < 32; c4++) {
            float4 qv = qrow[c4];
#pragma unroll
            for (int jj = 0; jj < 16; jj++) {
                float4 kv = *(const float4*)&Ks[(jg*16 + jj)*132 + c4*4];
                sum[jj] += qv.x*kv.x + qv.y*kv.y + qv.z*kv.z + qv.w*kv.w;
            }
        }
        const int gq = q0 + i_sc;
#pragma unroll
        for (int jj = 0; jj < 16; jj++) {
            int j = jg*16 + jj;
            int gk = kt*64 + j;
            Ss[i_sc*65 + j] = (gk <= gq) ? sum[jj] : -1e30f;
        }
        __syncthreads();

        // online softmax bookkeeping: one thread per row
        if (tid < 64) {
            float* row = &Ss[tid * 65];
            float mo = m_s[tid];
            float mloc = mo;
            for (int j = 0; j < 64; j++) mloc = fmaxf(mloc, row[j]);
            float alpha = __expf(mo - mloc);
            float ls = 0.f;
            for (int j = 0; j < 64; j++) {
                float pv = __expf(row[j] - mloc);
                row[j] = pv; ls += pv;
            }
            m_s[tid]  = mloc;
            l_s[tid]  = l_s[tid] * alpha + ls;
            al_s[tid] = alpha;
        }
        __syncthreads();

        // acc update: thread (i_sc, ck) owns 32 dims of its row
        float al = al_s[i_sc];
#pragma unroll
        for (int c = 0; c < 32; c++) acc[c] *= al;
        const float* srow = &Ss[i_sc * 65];
        for (int j = 0; j < 64; j++) {
            float pv = srow[j];
            const float4* vrow = (const float4*)&Vs[j*132 + ck*32];
#pragma unroll
            for (int c4 = 0; c4 < 8; c4++) {
                float4 vv = vrow[c4];
                acc[c4*4+0] += pv * vv.x;
                acc[c4*4+1] += pv * vv.y;
                acc[c4*4+2] += pv * vv.z;
                acc[c4*4+3] += pv * vv.w;
            }
        }
    }
    __syncthreads();
    const float inv = 1.f / l_s[i_sc];
    float* obase = osrc + (size_t)(b*T_ + q0 + i_sc)*D_ + h*DH_ + ck*32;
#pragma unroll
    for (int c4 = 0; c4 < 8; c4++) {
        float4 v;
        v.x = acc[c4*4+0]*inv; v.y = acc[c4*4+1]*inv;
        v.z = acc[c4*4+2]*inv; v.w = acc[c4*4+3]*inv;
        *(float4*)&obase[c4*4] = v;
    }
}

// ---------------------------------------------------------------------------
extern "C" void kernel_launch(void* const* d_in, const int* in_sizes, int n_in,
                              void* d_out, int out_size)
{
    const float* x   = (const float*)d_in[0];
    const float* l3m = (const float*)d_in[1];
    const float* wq  = (const float*)d_in[2];
    const float* wk  = (const float*)d_in[3];
    const float* wv  = (const float*)d_in[4];
    const float* wo  = (const float*)d_in[5];
    const float* rw1 = (const float*)d_in[6];
    const float* rb1 = (const float*)d_in[7];
    const float* rw2 = (const float*)d_in[8];
    const float* rb2 = (const float*)d_in[9];

    float* out  = (float*)d_out;
    float* khp  = out + (size_t)B_*T_*D_;        //  4194304
    float* vhp  = khp + (size_t)B_*T_*D_;        //  8388608
    float* lamp = vhp + (size_t)B_*T_*D_;        // 12582912

    float *qs, *l2s, *hdns, *fuseds, *attns;
    cudaGetSymbolAddress((void**)&qs,     g_q);
    cudaGetSymbolAddress((void**)&l2s,    g_l2);
    cudaGetSymbolAddress((void**)&hdns,   g_hdn);
    cudaGetSymbolAddress((void**)&fuseds, g_fused);
    cudaGetSymbolAddress((void**)&attns,  g_attn);

    dim3 blk(256);

    // q = x @ wq^T
    mma_gemm_tn<0,0><<<dim3(D_/128, (B_*T_)/128), blk>>>(x, wq, nullptr, qs, B_*T_, D_, D_);
    // l2 = causal EMA(x)
    ema_kernel<<<16, 256>>>(x, l2s);
    // hdn = silu(q @ rw1^T + rb1)
    mma_gemm_tn<0,1><<<dim3((D_/2)/128, (B_*T_)/128), blk>>>(qs, rw1, rb1, hdns, B_*T_, D_/2, D_);
    // lam + fused
    router_fuse<<<B_*T_, 256>>>(hdns, rw2, rb2, x, l2s, l3m, lamp, fuseds);
    // kh, vh (written transposed directly into output buffer)
    mma_gemm_tn<1,0><<<dim3(D_/128, (B_*T_)/128), blk>>>(fuseds, wk, nullptr, khp, B_*T_, D_, D_);
    mma_gemm_tn<1,0><<<dim3(D_/128, (B_*T_)/128), blk>>>(fuseds, wv, nullptr, vhp, B_*T_, D_, D_);
    // attention
    cudaFuncSetAttribute(attn_kernel, cudaFuncAttributeMaxDynamicSharedMemorySize, ATT_SMEM);
    attn_kernel<<<dim3(T_/64, B_*H_), blk, ATT_SMEM>>>(qs, khp, vhp, attns);
    // out = attn @ wo^T
    mma_gemm_tn<0,0><<<dim3(D_/128, (B_*T_)/128), blk>>>(attns, wo, nullptr, out, B_*T_, D_, D_);
}

// round 3
// speedup vs baseline: 1.2788x; 1.0494x over previous
#include <cuda_runtime.h>
#include <cuda_bf16.h>
#include <math.h>

// ---------------------------------------------------------------------------
// FastMKAAttention — round 3: pre-split bf16x3 GEMMs + cp.async double buffer
// shapes: b=2, t=1024, d=2048, h=16, dh=128
// output tuple (floats): out[4194304] | kh[4194304] | vh[4194304] | lam[6144]
// ---------------------------------------------------------------------------

#define B_   2
#define T_   1024
#define D_   2048
#define H_   16
#define DH_  128
#define MROWS (B_*T_)          // 2048
#define NELEM (B_*T_*D_)       // 4194304

// fp32 scratch
__device__ float g_q[NELEM];            // x @ wq^T (unscaled) — attention reads this
__device__ float g_l2[NELEM];           // EMA
__device__ float g_hdn[MROWS*(D_/2)];   // silu(q @ rw1^T + rb1)

// bf16 hi/lo scratch
__device__ __nv_bfloat16 g_x_hi[NELEM],    g_x_lo[NELEM];
__device__ __nv_bfloat16 g_wq_hi[D_*D_],   g_wq_lo[D_*D_];
__device__ __nv_bfloat16 g_wk_hi[D_*D_],   g_wk_lo[D_*D_];
__device__ __nv_bfloat16 g_wv_hi[D_*D_],   g_wv_lo[D_*D_];
__device__ __nv_bfloat16 g_wo_hi[D_*D_],   g_wo_lo[D_*D_];
__device__ __nv_bfloat16 g_rw1_hi[(D_/2)*D_], g_rw1_lo[(D_/2)*D_];
__device__ __nv_bfloat16 g_q_hi[NELEM],    g_q_lo[NELEM];
__device__ __nv_bfloat16 g_f_hi[NELEM],    g_f_lo[NELEM];
__device__ __nv_bfloat16 g_a_hi[NELEM],    g_a_lo[NELEM];

// ---------------------------------------------------------------------------
// helpers
// ---------------------------------------------------------------------------
__device__ __forceinline__ void split1(float v, __nv_bfloat16& hi, __nv_bfloat16& lo) {
    hi = __float2bfloat16(v);
    lo = __float2bfloat16(v - __bfloat162float(hi));
}

__device__ __forceinline__ void cp_async16(__nv_bfloat16* dst, const __nv_bfloat16* src) {
    unsigned s = (unsigned)__cvta_generic_to_shared(dst);
    asm volatile("cp.async.cg.shared.global [%0], [%1], 16;" :: "r"(s), "l"(src));
}
#define CP_COMMIT asm volatile("cp.async.commit_group;")
#define CP_WAIT0  asm volatile("cp.async.wait_group 0;")

__device__ __forceinline__ void mma_bf16(float* c, const unsigned* a, const unsigned* b) {
    asm volatile(
        "mma.sync.aligned.m16n8k16.row.col.f32.bf16.bf16.f32 "
        "{%0,%1,%2,%3}, {%4,%5,%6,%7}, {%8,%9}, {%0,%1,%2,%3};\n"
        : "+f"(c[0]), "+f"(c[1]), "+f"(c[2]), "+f"(c[3])
        : "r"(a[0]), "r"(a[1]), "r"(a[2]), "r"(a[3]), "r"(b[0]), "r"(b[1]));
}

// ---------------------------------------------------------------------------
// split kernel: fp32 -> bf16 hi/lo (n multiple of 4)
// ---------------------------------------------------------------------------
__global__ void split_kernel(const float* __restrict__ src,
                             __nv_bfloat16* __restrict__ hi,
                             __nv_bfloat16* __restrict__ lo, int n)
{
    int i = (blockIdx.x * blockDim.x + threadIdx.x) * 4;
    if (i >= n) return;
    float4 v = *(const float4*)(src + i);
    __nv_bfloat16 h[4], l[4];
    split1(v.x, h[0], l[0]); split1(v.y, h[1], l[1]);
    split1(v.z, h[2], l[2]); split1(v.w, h[3], l[3]);
    *(__nv_bfloat162*)(hi + i)     = __nv_bfloat162(h[0], h[1]);
    *(__nv_bfloat162*)(hi + i + 2) = __nv_bfloat162(h[2], h[3]);
    *(__nv_bfloat162*)(lo + i)     = __nv_bfloat162(l[0], l[1]);
    *(__nv_bfloat162*)(lo + i + 2) = __nv_bfloat162(l[2], l[3]);
}

// ---------------------------------------------------------------------------
// Tensor-core GEMM on pre-split bf16 hi/lo inputs.
//   C[m,n] = act( sum_k A[m,k]*B[n,k] (+bias[n]) )
// Block tile 128x128, BK=32, 256 threads (8 warps, 2x4), warp tile 64x32.
// cp.async double-buffered. MODE 0: row-major C; MODE 1: [b,h,t,dh] scatter.
// ACT 1: bias+silu. SPLIT 1: also emit bf16 hi/lo of C.
// ---------------------------------------------------------------------------
#define SSTR 40
#define HBYTES (128*SSTR)            // bf16 elems per half-tile
#define STAGE_ELEMS (4*HBYTES)       // 4 halves per stage
#define GEMM_SMEM (2*STAGE_ELEMS*2)  // bytes (2 stages, bf16)

__device__ __forceinline__ void stage_tile(
    const __nv_bfloat16* __restrict__ Ah, const __nv_bfloat16* __restrict__ Al,
    const __nv_bfloat16* __restrict__ Bh, const __nv_bfloat16* __restrict__ Bl,
    __nv_bfloat16* sbuf, int bm, int bn, int kt, int K, int tid)
{
    const __nv_bfloat16* gsrc[4];
    gsrc[0] = Ah + (size_t)bm * K + kt;
    gsrc[1] = Al + (size_t)bm * K + kt;
    gsrc[2] = Bh + (size_t)bn * K + kt;
    gsrc[3] = Bl + (size_t)bn * K + kt;
#pragma unroll
    for (int half = 0; half < 4; half++) {
        __nv_bfloat16* sd = sbuf + half * HBYTES;
        const __nv_bfloat16* gs = gsrc[half];
#pragma unroll
        for (int p = 0; p < 2; p++) {
            int idx = p * 256 + tid;
            int row = idx >> 2;
            int c8  = (idx & 3) * 8;
            cp_async16(sd + row * SSTR + c8, gs + (size_t)row * K + c8);
        }
    }
}

template<int MODE, int ACT, int SPLIT>
__global__ __launch_bounds__(256) void mma_gemm_tn(
    const __nv_bfloat16* __restrict__ Ah, const __nv_bfloat16* __restrict__ Al,
    const __nv_bfloat16* __restrict__ Bh, const __nv_bfloat16* __restrict__ Bl,
    const float* __restrict__ bias, float* __restrict__ C,
    __nv_bfloat16* __restrict__ Chi, __nv_bfloat16* __restrict__ Clo,
    int M, int N, int K)
{
    extern __shared__ __nv_bfloat16 smem[];

    const int tid  = threadIdx.x;
    const int lane = tid & 31;
    const int wid  = tid >> 5;
    const int wm   = wid >> 2;
    const int wn   = wid & 3;
    const int bm   = blockIdx.y * 128;
    const int bn   = blockIdx.x * 128;

    float acc[4][4][4];
#pragma unroll
    for (int i = 0; i < 4; i++)
#pragma unroll
        for (int j = 0; j < 4; j++)
#pragma unroll
            for (int r = 0; r < 4; r++) acc[i][j][r] = 0.f;

    const int nt = K / 32;
    stage_tile(Ah, Al, Bh, Bl, smem, bm, bn, 0, K, tid);
    CP_COMMIT;

    for (int it = 0; it < nt; it++) {
        CP_WAIT0;
        __syncthreads();
        if (it + 1 < nt) {
            stage_tile(Ah, Al, Bh, Bl, smem + ((it + 1) & 1) * STAGE_ELEMS,
                       bm, bn, (it + 1) * 32, K, tid);
            CP_COMMIT;
        }
        const __nv_bfloat16* buf = smem + (it & 1) * STAGE_ELEMS;
        const __nv_bfloat16* As_hi = buf;
        const __nv_bfloat16* As_lo = buf + HBYTES;
        const __nv_bfloat16* Bs_hi = buf + 2 * HBYTES;
        const __nv_bfloat16* Bs_lo = buf + 3 * HBYTES;

#pragma unroll
        for (int ks = 0; ks < 2; ks++) {
            const int kk = ks * 16 + (lane & 3) * 2;
            unsigned ahi[4][4], alo[4][4];
#pragma unroll
            for (int mf = 0; mf < 4; mf++) {
                int r0 = (wm * 64 + mf * 16 + (lane >> 2)) * SSTR;
                int r1 = r0 + 8 * SSTR;
                ahi[mf][0] = *(const unsigned*)&As_hi[r0 + kk];
                ahi[mf][1] = *(const unsigned*)&As_hi[r1 + kk];
                ahi[mf][2] = *(const unsigned*)&As_hi[r0 + kk + 8];
                ahi[mf][3] = *(const unsigned*)&As_hi[r1 + kk + 8];
                alo[mf][0] = *(const unsigned*)&As_lo[r0 + kk];
                alo[mf][1] = *(const unsigned*)&As_lo[r1 + kk];
                alo[mf][2] = *(const unsigned*)&As_lo[r0 + kk + 8];
                alo[mf][3] = *(const unsigned*)&As_lo[r1 + kk + 8];
            }
            unsigned bhi[4][2], blo[4][2];
#pragma unroll
            for (int nf = 0; nf < 4; nf++) {
                int c0 = (wn * 32 + nf * 8 + (lane >> 2)) * SSTR;
                bhi[nf][0] = *(const unsigned*)&Bs_hi[c0 + kk];
                bhi[nf][1] = *(const unsigned*)&Bs_hi[c0 + kk + 8];
                blo[nf][0] = *(const unsigned*)&Bs_lo[c0 + kk];
                blo[nf][1] = *(const unsigned*)&Bs_lo[c0 + kk + 8];
            }
#pragma unroll
            for (int mf = 0; mf < 4; mf++)
#pragma unroll
                for (int nf = 0; nf < 4; nf++) {
                    mma_bf16(acc[mf][nf], ahi[mf], bhi[nf]);
                    mma_bf16(acc[mf][nf], ahi[mf], blo[nf]);
                    mma_bf16(acc[mf][nf], alo[mf], bhi[nf]);
                }
        }
        __syncthreads();
    }

    // epilogue
#pragma unroll
    for (int mf = 0; mf < 4; mf++) {
#pragma unroll
        for (int nf = 0; nf < 4; nf++) {
            int m0 = bm + wm * 64 + mf * 16 + (lane >> 2);
            int n  = bn + wn * 32 + nf * 8 + (lane & 3) * 2;
#pragma unroll
            for (int half = 0; half < 2; half++) {
                int m = m0 + half * 8;
                float2 v;
                v.x = acc[mf][nf][half * 2 + 0];
                v.y = acc[mf][nf][half * 2 + 1];
                if (ACT == 1) {
                    v.x += bias[n];
                    v.y += bias[n + 1];
                    v.x = v.x / (1.f + __expf(-v.x));
                    v.y = v.y / (1.f + __expf(-v.y));
                }
                if (MODE == 0) {
                    size_t idx = (size_t)m * N + n;
                    if (C) *(float2*)&C[idx] = v;
                    if (SPLIT == 1) {
                        __nv_bfloat16 h0, l0, h1, l1;
                        split1(v.x, h0, l0);
                        split1(v.y, h1, l1);
                        *(__nv_bfloat162*)&Chi[idx] = __nv_bfloat162(h0, h1);
                        *(__nv_bfloat162*)&Clo[idx] = __nv_bfloat162(l0, l1);
                    }
                } else {
                    size_t idx = (size_t)(m >> 10) * (H_*T_*DH_) + (size_t)(n >> 7) * (T_*DH_)
                               + (size_t)(m & 1023) * DH_ + (n & 127);
                    *(float2*)&C[idx] = v;
                }
            }
        }
    }
}

// ---------------------------------------------------------------------------
// causal EMA: one thread per (b, d) channel; 1024 serial steps
// ---------------------------------------------------------------------------
__global__ void ema_kernel(const float* __restrict__ x, float* __restrict__ l2)
{
    int idx = blockIdx.x * blockDim.x + threadIdx.x;  // 0..4095
    int b = idx >> 11;
    int d = idx & (D_ - 1);
    const float beta = 0.9f, omb = 0.1f;
    size_t p = (size_t)b * T_ * D_ + d;
    float s = 0.f;
#pragma unroll 4
    for (int t = 0; t < T_; t++) {
        s = beta * s + omb * x[p];
        l2[p] = s;
        p += D_;
    }
}

// ---------------------------------------------------------------------------
// router (logits -> softmax over 3) + fused combine (emits bf16 hi/lo).
// ---------------------------------------------------------------------------
__global__ __launch_bounds__(256) void router_fuse(
    const float* __restrict__ hdn, const float* __restrict__ rw2,
    const float* __restrict__ rb2, const float* __restrict__ x,
    const float* __restrict__ l2, const float* __restrict__ l3m,
    float* __restrict__ lam_out,
    __nv_bfloat16* __restrict__ fhi, __nv_bfloat16* __restrict__ flo)
{
    const int m = blockIdx.x;
    const int tid = threadIdx.x;
    const int HD = D_ / 2;  // 1024

    const float* hrow = hdn + (size_t)m * HD;
    float s0 = 0.f, s1 = 0.f, s2 = 0.f;
    for (int k = tid; k < HD; k += 256) {
        float hv = hrow[k];
        s0 += hv * rw2[k];
        s1 += hv * rw2[HD + k];
        s2 += hv * rw2[2*HD + k];
    }
#pragma unroll
    for (int o = 16; o > 0; o >>= 1) {
        s0 += __shfl_down_sync(0xffffffffu, s0, o);
        s1 += __shfl_down_sync(0xffffffffu, s1, o);
        s2 += __shfl_down_sync(0xffffffffu, s2, o);
    }
    __shared__ float red[8][3];
    __shared__ float lam_s[3];
    if ((tid & 31) == 0) {
        red[tid >> 5][0] = s0; red[tid >> 5][1] = s1; red[tid >> 5][2] = s2;
    }
    __syncthreads();
    if (tid == 0) {
        float L0 = rb2[0], L1 = rb2[1], L2v = rb2[2];
        for (int w = 0; w < 8; w++) { L0 += red[w][0]; L1 += red[w][1]; L2v += red[w][2]; }
        float mx = fmaxf(L0, fmaxf(L1, L2v));
        float e0 = __expf(L0 - mx), e1 = __expf(L1 - mx), e2 = __expf(L2v - mx);
        float inv = 1.f / (e0 + e1 + e2);
        lam_s[0] = e0 * inv; lam_s[1] = e1 * inv; lam_s[2] = e2 * inv;
        lam_out[m*3+0] = lam_s[0]; lam_out[m*3+1] = lam_s[1]; lam_out[m*3+2] = lam_s[2];
    }
    __syncthreads();
    const float la = lam_s[0], lb = lam_s[1], lc = lam_s[2];
    const int b = m >> 10;
    const float4* xr  = (const float4*)(x  + (size_t)m * D_);
    const float4* l2r = (const float4*)(l2 + (size_t)m * D_);
    const float4* l3r = (const float4*)(l3m + (size_t)b * D_);
    for (int q = tid; q < D_/4; q += 256) {
        float4 xv = xr[q], l2v = l2r[q], l3v = l3r[q];
        float o0 = la*xv.x + lb*l2v.x + lc*l3v.x;
        float o1 = la*xv.y + lb*l2v.y + lc*l3v.y;
        float o2 = la*xv.z + lb*l2v.z + lc*l3v.z;
        float o3 = la*xv.w + lb*l2v.w + lc*l3v.w;
        __nv_bfloat16 h0,l0,h1,l1,h2,l2b,h3,l3;
        split1(o0,h0,l0); split1(o1,h1,l1); split1(o2,h2,l2b); split1(o3,h3,l3);
        size_t base = (size_t)m * D_ + q * 4;
        *(__nv_bfloat162*)&fhi[base]     = __nv_bfloat162(h0, h1);
        *(__nv_bfloat162*)&fhi[base + 2] = __nv_bfloat162(h2, h3);
        *(__nv_bfloat162*)&flo[base]     = __nv_bfloat162(l0, l1);
        *(__nv_bfloat162*)&flo[base + 2] = __nv_bfloat162(l2b, l3);
    }
}

// ---------------------------------------------------------------------------
// flash-style causal attention (fp32). Emits attn output as bf16 hi/lo.
// ---------------------------------------------------------------------------
#define ATT_SMEM ((3*64*132 + 64*65 + 3*64) * 4)

__global__ __launch_bounds__(256) void attn_kernel(
    const float* __restrict__ qsrc, const float* __restrict__ kh,
    const float* __restrict__ vh,
    __nv_bfloat16* __restrict__ ohi, __nv_bfloat16* __restrict__ olo)
{
    extern __shared__ float sm[];
    float* Qs  = sm;                 // 64 * 132
    float* Ks  = Qs + 64*132;
    float* Vs  = Ks + 64*132;
    float* Ss  = Vs + 64*132;        // 64 * 65
    float* m_s = Ss + 64*65;
    float* l_s = m_s + 64;
    float* al_s= l_s + 64;

    const int tid = threadIdx.x;
    const int qt = blockIdx.x, bh = blockIdx.y;
    const int b = bh >> 4, h = bh & 15;
    const int q0 = qt * 64;
    const float scale = 0.08838834764831845f;  // 1/sqrt(128)

#pragma unroll
    for (int p = 0; p < 8; p++) {
        int f = p * 256 + tid;
        int i = f >> 5, c4 = f & 31;
        float4 v = *(const float4*)&qsrc[(size_t)(b*T_ + q0 + i)*D_ + h*DH_ + c4*4];
        v.x *= scale; v.y *= scale; v.z *= scale; v.w *= scale;
        *(float4*)&Qs[i*132 + c4*4] = v;
    }
    if (tid < 64) { m_s[tid] = -1e30f; l_s[tid] = 0.f; }

    float acc[32];
#pragma unroll
    for (int c = 0; c < 32; c++) acc[c] = 0.f;

    const int i_sc = tid >> 2;
    const int jg   = tid & 3;
    const int ck   = tid & 3;

    const float* kbase = kh + (size_t)(b*H_ + h) * T_ * DH_;
    const float* vbase = vh + (size_t)(b*H_ + h) * T_ * DH_;

    for (int kt = 0; kt <= qt; kt++) {
        __syncthreads();
#pragma unroll
        for (int p = 0; p < 8; p++) {
            int f = p * 256 + tid;
            int j = f >> 5, c4 = f & 31;
            *(float4*)&Ks[j*132 + c4*4] = *(const float4*)&kbase[(size_t)(kt*64 + j)*DH_ + c4*4];
            *(float4*)&Vs[j*132 + c4*4] = *(const float4*)&vbase[(size_t)(kt*64 + j)*DH_ + c4*4];
        }
        __syncthreads();

        float sum[16];
#pragma unroll
        for (int jj = 0; jj < 16; jj++) sum[jj] = 0.f;
        const float4* qrow = (const float4*)&Qs[i_sc * 132];
        for (int c4 = 0; c4 < 32; c4++) {
            float4 qv = qrow[c4];
#pragma unroll
            for (int jj = 0; jj < 16; jj++) {
                float4 kv = *(const float4*)&Ks[(jg*16 + jj)*132 + c4*4];
                sum[jj] += qv.x*kv.x + qv.y*kv.y + qv.z*kv.z + qv.w*kv.w;
            }
        }
        const int gq = q0 + i_sc;
#pragma unroll
        for (int jj = 0; jj < 16; jj++) {
            int j = jg*16 + jj;
            int gk = kt*64 + j;
            Ss[i_sc*65 + j] = (gk <= gq) ? sum[jj] : -1e30f;
        }
        __syncthreads();

        if (tid < 64) {
            float* row = &Ss[tid * 65];
            float mo = m_s[tid];
            float mloc = mo;
            for (int j = 0; j < 64; j++) mloc = fmaxf(mloc, row[j]);
            float alpha = __expf(mo - mloc);
            float ls = 0.f;
            for (int j = 0; j < 64; j++) {
                float pv = __expf(row[j] - mloc);
                row[j] = pv; ls += pv;
            }
            m_s[tid]  = mloc;
            l_s[tid]  = l_s[tid] * alpha + ls;
            al_s[tid] = alpha;
        }
        __syncthreads();

        float al = al_s[i_sc];
#pragma unroll
        for (int c = 0; c < 32; c++) acc[c] *= al;
        const float* srow = &Ss[i_sc * 65];
        for (int j = 0; j < 64; j++) {
            float pv = srow[j];
            const float4* vrow = (const float4*)&Vs[j*132 + ck*32];
#pragma unroll
            for (int c4 = 0; c4 < 8; c4++) {
                float4 vv = vrow[c4];
                acc[c4*4+0] += pv * vv.x;
                acc[c4*4+1] += pv * vv.y;
                acc[c4*4+2] += pv * vv.z;
                acc[c4*4+3] += pv * vv.w;
            }
        }
    }
    __syncthreads();
    const float inv = 1.f / l_s[i_sc];
    size_t obase = (size_t)(b*T_ + q0 + i_sc)*D_ + h*DH_ + ck*32;
#pragma unroll
    for (int c4 = 0; c4 < 8; c4++) {
        float v0 = acc[c4*4+0]*inv, v1 = acc[c4*4+1]*inv;
        float v2 = acc[c4*4+2]*inv, v3 = acc[c4*4+3]*inv;
        __nv_bfloat16 h0,l0,h1,l1,h2,l2,h3,l3;
        split1(v0,h0,l0); split1(v1,h1,l1); split1(v2,h2,l2); split1(v3,h3,l3);
        *(__nv_bfloat162*)&ohi[obase + c4*4]     = __nv_bfloat162(h0, h1);
        *(__nv_bfloat162*)&ohi[obase + c4*4 + 2] = __nv_bfloat162(h2, h3);
        *(__nv_bfloat162*)&olo[obase + c4*4]     = __nv_bfloat162(l0, l1);
        *(__nv_bfloat162*)&olo[obase + c4*4 + 2] = __nv_bfloat162(l2, l3);
    }
}

// ---------------------------------------------------------------------------
extern "C" void kernel_launch(void* const* d_in, const int* in_sizes, int n_in,
                              void* d_out, int out_size)
{
    const float* x   = (const float*)d_in[0];
    const float* l3m = (const float*)d_in[1];
    const float* wq  = (const float*)d_in[2];
    const float* wk  = (const float*)d_in[3];
    const float* wv  = (const float*)d_in[4];
    const float* wo  = (const float*)d_in[5];
    const float* rw1 = (const float*)d_in[6];
    const float* rb1 = (const float*)d_in[7];
    const float* rw2 = (const float*)d_in[8];
    const float* rb2 = (const float*)d_in[9];

    float* out  = (float*)d_out;
    float* khp  = out + (size_t)NELEM;
    float* vhp  = khp + (size_t)NELEM;
    float* lamp = vhp + (size_t)NELEM;

    float *qs, *l2s, *hdns;
    cudaGetSymbolAddress((void**)&qs,   g_q);
    cudaGetSymbolAddress((void**)&l2s,  g_l2);
    cudaGetSymbolAddress((void**)&hdns, g_hdn);
    __nv_bfloat16 *xh,*xl,*wqh,*wql,*wkh,*wkl,*wvh,*wvl,*woh,*wol,*r1h,*r1l;
    __nv_bfloat16 *qh,*ql,*fh,*fl,*ah,*al;
    cudaGetSymbolAddress((void**)&xh,  g_x_hi);  cudaGetSymbolAddress((void**)&xl,  g_x_lo);
    cudaGetSymbolAddress((void**)&wqh, g_wq_hi); cudaGetSymbolAddress((void**)&wql, g_wq_lo);
    cudaGetSymbolAddress((void**)&wkh, g_wk_hi); cudaGetSymbolAddress((void**)&wkl, g_wk_lo);
    cudaGetSymbolAddress((void**)&wvh, g_wv_hi); cudaGetSymbolAddress((void**)&wvl, g_wv_lo);
    cudaGetSymbolAddress((void**)&woh, g_wo_hi); cudaGetSymbolAddress((void**)&wol, g_wo_lo);
    cudaGetSymbolAddress((void**)&r1h, g_rw1_hi);cudaGetSymbolAddress((void**)&r1l, g_rw1_lo);
    cudaGetSymbolAddress((void**)&qh,  g_q_hi);  cudaGetSymbolAddress((void**)&ql,  g_q_lo);
    cudaGetSymbolAddress((void**)&fh,  g_f_hi);  cudaGetSymbolAddress((void**)&fl,  g_f_lo);
    cudaGetSymbolAddress((void**)&ah,  g_a_hi);  cudaGetSymbolAddress((void**)&al,  g_a_lo);

    dim3 blk(256);

    // smem attributes
    cudaFuncSetAttribute(mma_gemm_tn<0,0,1>, cudaFuncAttributeMaxDynamicSharedMemorySize, GEMM_SMEM);
    cudaFuncSetAttribute(mma_gemm_tn<0,0,0>, cudaFuncAttributeMaxDynamicSharedMemorySize, GEMM_SMEM);
    cudaFuncSetAttribute(mma_gemm_tn<0,1,0>, cudaFuncAttributeMaxDynamicSharedMemorySize, GEMM_SMEM);
    cudaFuncSetAttribute(mma_gemm_tn<1,0,0>, cudaFuncAttributeMaxDynamicSharedMemorySize, GEMM_SMEM);
    cudaFuncSetAttribute(attn_kernel, cudaFuncAttributeMaxDynamicSharedMemorySize, ATT_SMEM);

    // pre-split inputs
    split_kernel<<<NELEM/1024, 256>>>(x,   xh,  xl,  NELEM);
    split_kernel<<<(D_*D_)/1024, 256>>>(wq, wqh, wql, D_*D_);
    split_kernel<<<(D_*D_)/1024, 256>>>(wk, wkh, wkl, D_*D_);
    split_kernel<<<(D_*D_)/1024, 256>>>(wv, wvh, wvl, D_*D_);
    split_kernel<<<(D_*D_)/1024, 256>>>(wo, woh, wol, D_*D_);
    split_kernel<<<((D_/2)*D_)/1024, 256>>>(rw1, r1h, r1l, (D_/2)*D_);

    // q = x @ wq^T  (fp32 + hi/lo)
    mma_gemm_tn<0,0,1><<<dim3(D_/128, MROWS/128), blk, GEMM_SMEM>>>(
        xh, xl, wqh, wql, nullptr, qs, qh, ql, MROWS, D_, D_);
    // l2 = causal EMA(x)
    ema_kernel<<<16, 256>>>(x, l2s);
    // hdn = silu(q @ rw1^T + rb1)
    mma_gemm_tn<0,1,0><<<dim3((D_/2)/128, MROWS/128), blk, GEMM_SMEM>>>(
        qh, ql, r1h, r1l, rb1, hdns, nullptr, nullptr, MROWS, D_/2, D_);
    // lam + fused (bf16 hi/lo)
    router_fuse<<<MROWS, 256>>>(hdns, rw2, rb2, x, l2s, l3m, lamp, fh, fl);
    // kh, vh (scattered [b,h,t,dh] into output buffer)
    mma_gemm_tn<1,0,0><<<dim3(D_/128, MROWS/128), blk, GEMM_SMEM>>>(
        fh, fl, wkh, wkl, nullptr, khp, nullptr, nullptr, MROWS, D_, D_);
    mma_gemm_tn<1,0,0><<<dim3(D_/128, MROWS/128), blk, GEMM_SMEM>>>(
        fh, fl, wvh, wvl, nullptr, vhp, nullptr, nullptr, MROWS, D_, D_);
    // attention (fp32 compute, bf16 hi/lo output)
    attn_kernel<<<dim3(T_/64, B_*H_), blk, ATT_SMEM>>>(qs, khp, vhp, ah, al);
    // out = attn @ wo^T
    mma_gemm_tn<0,0,0><<<dim3(D_/128, MROWS/128), blk, GEMM_SMEM>>>(
        ah, al, woh, wol, nullptr, out, nullptr, nullptr, MROWS, D_, D_);
}